// round 15
// baseline (speedup 1.0000x reference)
#include <cuda_runtime.h>
#include <cuda_bf16.h>
#include <cuda_fp16.h>
#include <cstdint>

// Problem constants
#define Bc  2
#define Sc  2048
#define Dc  2048
#define Hc  16
#define HDc 128
#define QRc 12
#define Rc  2

// Fused projection column offsets: [WAq | WAk | WAv | WBq | WBk | WBv]
#define NTOT 2304
#define OAq  0
#define OAk  192
#define OAv  224
#define OBq  256
#define OBk  1792
#define OBv  2048

// ---------------------------------------------------------------------------
// Device scratch (no cudaMalloc allowed).
// ---------------------------------------------------------------------------
__device__ __half g_x  [(size_t)Bc*Sc*Dc];
__device__ __half g_WT [(size_t)NTOT*Dc];
__device__ __half g_WoT[(size_t)Dc*Dc];
__device__ float g_proj[(size_t)Bc*Sc*NTOT];
__device__ __half g_q  [(size_t)Bc*Sc*Hc*HDc];
__device__ __half g_k  [(size_t)Bc*Sc*Hc*HDc];
__device__ __half g_v  [(size_t)Bc*Sc*Hc*HDc];
__device__ __half g_vT [(size_t)Bc*Hc*HDc*Sc];
__device__ __half g_att[(size_t)Bc*Sc*Hc*HDc];

// ---------------------------------------------------------------------------
// Helpers
// ---------------------------------------------------------------------------
__device__ __forceinline__ uint32_t s2u(const void* p) {
    return (uint32_t)__cvta_generic_to_shared(p);
}
__device__ __forceinline__ void cp16(uint32_t dst, const void* src) {
    asm volatile("cp.async.cg.shared.global [%0], [%1], 16;\n"
                 :: "r"(dst), "l"(src));
}
__device__ __forceinline__ uint32_t packh(float a, float b) {
    __half2 t = __floats2half2_rn(a, b);
    return *(uint32_t*)&t;
}
// Two fp16 exps in one MUFU op: d = 2^(f16x2 of (a,b))
__device__ __forceinline__ uint32_t ex2h2(float a, float b) {
    uint32_t arg, r;
    asm("cvt.rn.f16x2.f32 %0, %1, %2;" : "=r"(arg) : "f"(b), "f"(a));
    asm("ex2.approx.f16x2 %0, %1;" : "=r"(r) : "r"(arg));
    return r;
}

// fp16 mma
#define HMMA(d, a, b) asm volatile( \
    "mma.sync.aligned.m16n8k16.row.col.f32.f16.f16.f32 " \
    "{%0,%1,%2,%3}, {%4,%5,%6,%7}, {%8,%9}, {%0,%1,%2,%3};" \
    : "+f"((d)[0]), "+f"((d)[1]), "+f"((d)[2]), "+f"((d)[3]) \
    : "r"((a)[0]), "r"((a)[1]), "r"((a)[2]), "r"((a)[3]), \
      "r"((b)[0]), "r"((b)[1]))

// ---------------------------------------------------------------------------
// Elementwise convert: fp32 -> fp16. n4 = elements/4.
// ---------------------------------------------------------------------------
__global__ void cvt_kernel(const float* __restrict__ src,
                           __half* __restrict__ dst, long long n4)
{
    long long i = (long long)blockIdx.x * blockDim.x + threadIdx.x;
    if (i >= n4) return;
    float4 f = ((const float4*)src)[i];
    ((__half2*)dst)[2*i]   = __floats2half2_rn(f.x, f.y);
    ((__half2*)dst)[2*i+1] = __floats2half2_rn(f.z, f.w);
}

// ---------------------------------------------------------------------------
// Merged transpose of ALL weights to fp16 [N][K] rows in one launch.
// ---------------------------------------------------------------------------
__global__ void tsplit_all_kernel(const float* __restrict__ W0,
                                  const float* __restrict__ W1,
                                  const float* __restrict__ W2,
                                  const float* __restrict__ W3,
                                  const float* __restrict__ W4,
                                  const float* __restrict__ W5,
                                  const float* __restrict__ W6,
                                  __half* __restrict__ WT,
                                  __half* __restrict__ WoT)
{
    const int segStart[8] = {0, 192, 224, 256, 1792, 2048, 2304, 4352};
    const float* srcs[7]  = {W0, W1, W2, W3, W4, W5, W6};
    const int Ns[7]       = {192, 32, 32, 1536, 256, 256, 2048};

    int cg = blockIdx.x * 32;
    int seg = 0;
#pragma unroll
    for (int s = 0; s < 6; s++)
        if (cg >= segStart[s + 1]) seg = s + 1;

    const float* W = srcs[seg];
    int N  = Ns[seg];
    int n0 = cg - segStart[seg];
    int k0 = blockIdx.y * 32;

    __shared__ float tile[32][33];
    int tx = threadIdx.x, ty = threadIdx.y;
    for (int r = ty; r < 32; r += 8)
        tile[r][tx] = W[(size_t)(k0 + r) * N + n0 + tx];
    __syncthreads();

    if (seg < 6) {
        for (int r = ty; r < 32; r += 8)
            WT[(size_t)(cg + r) * Dc + k0 + tx] = __float2half_rn(tile[tx][r]);
    } else {
        for (int r = ty; r < 32; r += 8)
            WoT[(size_t)(n0 + r) * Dc + k0 + tx] = __float2half_rn(tile[tx][r]);
    }
}

// ---------------------------------------------------------------------------
// Single-mma fp16 tensor-core GEMM (validated round 12, unchanged).
// ---------------------------------------------------------------------------
#define GBM 128
#define GBN 128
#define GBK 32
#define LDW 20
#define TW  (128 * LDW)
#define GSMEM_BYTES (2 * 2 * TW * 4) // 40960

__global__ __launch_bounds__(256) void f16_gemm_kernel(
    const __half* __restrict__ Ah, const __half* __restrict__ Bh,
    float* __restrict__ C, int M, int N, int K, int ldc)
{
    extern __shared__ uint32_t gs[];

    int m0 = blockIdx.y * GBM;
    int n0 = blockIdx.x * GBN;
    int tid = threadIdx.x, warp = tid >> 5, lane = tid & 31;
    int wm = warp >> 2, wn = warp & 3;
    int g  = lane >> 2, tg = lane & 3;

    float acc[4][4][4];
#pragma unroll
    for (int i = 0; i < 4; i++)
#pragma unroll
        for (int j = 0; j < 4; j++)
#pragma unroll
            for (int c = 0; c < 4; c++) acc[i][j][c] = 0.f;

    auto stage = [&](int kt, int buf) {
        uint32_t* base = gs + buf * 2 * TW;
        const __half* srcs[2] = {Ah, Bh};
#pragma unroll
        for (int t = 0; t < 2; t++) {
            const __half* S = srcs[t];
            int r0 = (t < 1) ? m0 : n0;
            uint32_t* dst = base + t * TW;
#pragma unroll
            for (int l = 0; l < 2; l++) {
                int v = tid + l * 256;
                int row = v >> 2, cq = v & 3;
                cp16(s2u(dst + row * LDW + cq * 4),
                     S + (size_t)(r0 + row) * K + kt + cq * 8);
            }
        }
    };

    stage(0, 0);
    asm volatile("cp.async.commit_group;");

    int buf = 0;
    for (int kt = 0; kt < K; kt += GBK, buf ^= 1) {
        if (kt + GBK < K) {
            stage(kt + GBK, buf ^ 1);
            asm volatile("cp.async.commit_group;");
            asm volatile("cp.async.wait_group 1;");
        } else {
            asm volatile("cp.async.wait_group 0;");
        }
        __syncthreads();

        const uint32_t* cA = gs + buf * 2 * TW;
        const uint32_t* cB = cA + TW;

#pragma unroll
        for (int ks = 0; ks < 2; ks++) {
            int kw = ks * 8;
            uint32_t ah[4][4], bh[4][2];
#pragma unroll
            for (int i = 0; i < 4; i++) {
                int b0 = (wm * 64 + i * 16 + g) * LDW + kw + tg;
                int b1 = b0 + 8 * LDW;
                ah[i][0] = cA[b0]; ah[i][1] = cA[b1];
                ah[i][2] = cA[b0 + 4]; ah[i][3] = cA[b1 + 4];
            }
#pragma unroll
            for (int j = 0; j < 4; j++) {
                int bb = (wn * 32 + j * 8 + g) * LDW + kw + tg;
                bh[j][0] = cB[bb]; bh[j][1] = cB[bb + 4];
            }
#pragma unroll
            for (int i = 0; i < 4; i++)
#pragma unroll
                for (int j = 0; j < 4; j++)
                    HMMA(acc[i][j], ah[i], bh[j]);
        }
        __syncthreads();
    }

#pragma unroll
    for (int i = 0; i < 4; i++) {
        int row = m0 + wm * 64 + i * 16 + g;
#pragma unroll
        for (int j = 0; j < 4; j++) {
            int col = n0 + wn * 32 + j * 8 + 2 * tg;
            *(float2*)(C + (size_t)row * ldc + col) =
                make_float2(acc[i][j][0], acc[i][j][1]);
            *(float2*)(C + (size_t)(row + 8) * ldc + col) =
                make_float2(acc[i][j][2], acc[i][j][3]);
        }
    }
}

// ---------------------------------------------------------------------------
// Fused RoPE + rank combine -> q, k, v fp16 (b,s,h,d). Scales folded.
// One thread per (b,s,h,d-pair); rope applied inline (same fp32 math as the
// previous separate rope pass).
// ---------------------------------------------------------------------------
__global__ void combine_kernel(const float* __restrict__ proj,
                               const float* __restrict__ fcos,
                               const float* __restrict__ fsin,
                               __half* __restrict__ q, __half* __restrict__ k,
                               __half* __restrict__ v)
{
    long long idx = (long long)blockIdx.x * blockDim.x + threadIdx.x;
    const long long total = (long long)Bc * Sc * Hc * (HDc / 2);
    if (idx >= total) return;
    int i = (int)(idx % (HDc / 2));
    int h = (int)((idx / (HDc / 2)) % Hc);
    long long bs = idx / ((long long)(HDc / 2) * Hc);
    const float* row = proj + bs * NTOT;
    long long s = bs % Sc;
    float co = fcos[s * (HDc / 2) + i];
    float sn = fsin[s * (HDc / 2) + i];
    int d0 = 2 * i;

    float q0 = 0.f, q1 = 0.f;
#pragma unroll
    for (int r = 0; r < QRc; r++) {
        float a  = row[OAq + h * QRc + r];
        float b0 = row[OBq + r * HDc + d0];
        float b1 = row[OBq + r * HDc + d0 + 1];
        q0 += a * (b0 * co - b1 * sn);
        q1 += a * (b0 * sn + b1 * co);
    }
    const float qs = (1.0f / QRc) * 0.08838834764831845f;
    size_t base = (bs * Hc + h) * (size_t)HDc + d0;
    *(__half2*)(q + base) = __floats2half2_rn(q0 * qs, q1 * qs);

    float k0 = 0.f, k1 = 0.f, v0 = 0.f, v1 = 0.f;
#pragma unroll
    for (int r = 0; r < Rc; r++) {
        float ak = row[OAk + h * Rc + r];
        float b0 = row[OBk + r * HDc + d0];
        float b1 = row[OBk + r * HDc + d0 + 1];
        k0 += ak * (b0 * co - b1 * sn);
        k1 += ak * (b0 * sn + b1 * co);
        float av = row[OAv + h * Rc + r];
        v0 += av * row[OBv + r * HDc + d0];
        v1 += av * row[OBv + r * HDc + d0 + 1];
    }
    *(__half2*)(k + base) = __floats2half2_rn(k0 * (1.0f / Rc), k1 * (1.0f / Rc));
    *(__half2*)(v + base) = __floats2half2_rn(v0 * (1.0f / Rc), v1 * (1.0f / Rc));
}

// ---------------------------------------------------------------------------
// V transpose: (b,s,h,d) -> (b,h,d,s), fp16.
// ---------------------------------------------------------------------------
__global__ void vtrans_kernel(const __half* __restrict__ v,
                              __half* __restrict__ vT)
{
    __shared__ __half th[32][34];
    int s0 = blockIdx.x * 32, d0 = blockIdx.y * 32;
    int bh = blockIdx.z;
    int b = bh / Hc, h = bh % Hc;
    int tx = threadIdx.x, ty = threadIdx.y;
    for (int r = ty; r < 32; r += 8)
        th[r][tx] = v[(((size_t)b * Sc + s0 + r) * Hc + h) * HDc + d0 + tx];
    __syncthreads();
    for (int r = ty; r < 32; r += 8)
        vT[((size_t)bh * HDc + d0 + r) * Sc + s0 + tx] = th[tx][r];
}

// ---------------------------------------------------------------------------
// Fused causal flash attention, single-mma fp16, DOUBLE-BUFFERED K/V.
// Prefetch tile t+1 while computing tile t; wait_group lands after compute.
// smem: Q + 2x(K,V) = 89088 B -> 2 CTAs/SM.
// ---------------------------------------------------------------------------
#define FLDQ 68
#define FLDV 36
#define FQW  (64 * FLDQ)             // 4352 words
#define FVW  (128 * FLDV)            // 4608 words
#define FSMEM_BYTES ((3 * FQW + 2 * FVW) * 4)   // 89088

__global__ __launch_bounds__(128) void flash_kernel(
    const __half* __restrict__ q, const __half* __restrict__ kk_,
    const __half* __restrict__ vT, __half* __restrict__ att)
{
    extern __shared__ uint32_t fs[];
    uint32_t* wQ = fs;
    uint32_t* wKb[2] = { fs + FQW, fs + 2 * FQW };
    uint32_t* wVb[2] = { fs + 3 * FQW, fs + 3 * FQW + FVW };

    int mt = gridDim.x - 1 - blockIdx.x;     // long blocks first
    int m0 = mt * 64;
    int bh = blockIdx.y;
    int b  = bh / Hc, h = bh % Hc;

    int tid  = threadIdx.x;
    int warp = tid >> 5, lane = tid & 31;
    int g = lane >> 2, tg = lane & 3;
    int rowbase = warp * 16;

    const float L2E = 1.4426950408889634f;

    auto stageKV = [&](int n0, int bufb) {
        uint32_t* dK = wKb[bufb];
        uint32_t* dV = wVb[bufb];
#pragma unroll
        for (int l = 0; l < 8; l++) {
            int v = tid + l * 128;
            int row = v >> 4, cq = v & 15;
            size_t src = (((size_t)b * Sc + n0 + row) * Hc + h) * HDc + cq * 8;
            cp16(s2u(dK + row * FLDQ + cq * 4), kk_ + src);
        }
#pragma unroll
        for (int l = 0; l < 8; l++) {
            int v = tid + l * 128;
            int row = v >> 3, cq = v & 7;
            size_t src = ((size_t)bh * HDc + row) * Sc + n0 + cq * 8;
            cp16(s2u(dV + row * FLDV + cq * 4), vT + src);
        }
    };

    // ---- initial: stage Q and KV(0), drain fully ----
#pragma unroll
    for (int l = 0; l < 8; l++) {
        int v = tid + l * 128;
        int row = v >> 4, cq = v & 15;
        size_t src = (((size_t)b * Sc + m0 + row) * Hc + h) * HDc + cq * 8;
        cp16(s2u(wQ + row * FLDQ + cq * 4), q + src);
    }
    stageKV(0, 0);
    asm volatile("cp.async.commit_group;");
    asm volatile("cp.async.wait_group 0;");
    __syncthreads();

    float acc[16][4];
#pragma unroll
    for (int j = 0; j < 16; j++)
#pragma unroll
        for (int c = 0; c < 4; c++) acc[j][c] = 0.f;
    float m_a = -1e30f, m_b = -1e30f, l_a = 0.f, l_b = 0.f;

    int buf = 0;
    for (int t = 0; t <= mt; t++) {
        // ---- prefetch next tile into the other buffer ----
        if (t < mt) {
            stageKV((t + 1) * 64, buf ^ 1);
            asm volatile("cp.async.commit_group;");
        }

        const uint32_t* wK = wKb[buf];
        const uint32_t* wV = wVb[buf];

        // ---- S = Q K^T, 8 n-tiles of n8, 1 mma each ----
        float c[8][4];
#pragma unroll
        for (int n = 0; n < 8; n++)
#pragma unroll
            for (int i = 0; i < 4; i++) c[n][i] = 0.f;

#pragma unroll
        for (int kk = 0; kk < 8; kk++) {
            uint32_t ah[4];
            int ra = (rowbase + g) * FLDQ + kk * 8 + tg;
            int rb = (rowbase + g + 8) * FLDQ + kk * 8 + tg;
            ah[0] = wQ[ra]; ah[1] = wQ[rb]; ah[2] = wQ[ra + 4]; ah[3] = wQ[rb + 4];
#pragma unroll
            for (int n = 0; n < 8; n++) {
                int rk = (n * 8 + g) * FLDQ + kk * 8 + tg;
                uint32_t bf[2] = { wK[rk], wK[rk + 4] };
                HMMA(c[n], ah, bf);
            }
        }

        // ---- causal mask on the diagonal tile ----
        if (t == mt) {
            int ra = rowbase + g, rb = ra + 8;
#pragma unroll
            for (int n = 0; n < 8; n++) {
                int c0 = n * 8 + 2 * tg, c1 = c0 + 1;
                if (c0 > ra) c[n][0] = -1e30f;
                if (c1 > ra) c[n][1] = -1e30f;
                if (c0 > rb) c[n][2] = -1e30f;
                if (c1 > rb) c[n][3] = -1e30f;
            }
        }

        // ---- online softmax: max in fp32, exp via ex2.f16x2 ----
        float mxa = -1e30f, mxb = -1e30f;
#pragma unroll
        for (int n = 0; n < 8; n++) {
            mxa = fmaxf(mxa, fmaxf(c[n][0], c[n][1]));
            mxb = fmaxf(mxb, fmaxf(c[n][2], c[n][3]));
        }
        mxa = fmaxf(mxa, __shfl_xor_sync(0xFFFFFFFFu, mxa, 1));
        mxa = fmaxf(mxa, __shfl_xor_sync(0xFFFFFFFFu, mxa, 2));
        mxb = fmaxf(mxb, __shfl_xor_sync(0xFFFFFFFFu, mxb, 1));
        mxb = fmaxf(mxb, __shfl_xor_sync(0xFFFFFFFFu, mxb, 2));

        float mna = fmaxf(m_a, mxa), mnb = fmaxf(m_b, mxb);
        float esa = __expf(m_a - mna), esb = __expf(m_b - mnb);
        m_a = mna; m_b = mnb;

        float na = mna * L2E, nb = mnb * L2E;
        uint32_t Pa[8], Pb[8];
        __half2 sa = __floats2half2_rn(0.f, 0.f);
        __half2 sb = sa;
#pragma unroll
        for (int n = 0; n < 8; n++) {
            Pa[n] = ex2h2(fmaf(c[n][0], L2E, -na), fmaf(c[n][1], L2E, -na));
            Pb[n] = ex2h2(fmaf(c[n][2], L2E, -nb), fmaf(c[n][3], L2E, -nb));
            sa = __hadd2(sa, *(__half2*)&Pa[n]);
            sb = __hadd2(sb, *(__half2*)&Pb[n]);
        }
        float2 fa = __half22float2(sa);
        float2 fb = __half22float2(sb);
        float suma = fa.x + fa.y;
        float sumb = fb.x + fb.y;
        suma += __shfl_xor_sync(0xFFFFFFFFu, suma, 1);
        suma += __shfl_xor_sync(0xFFFFFFFFu, suma, 2);
        sumb += __shfl_xor_sync(0xFFFFFFFFu, sumb, 1);
        sumb += __shfl_xor_sync(0xFFFFFFFFu, sumb, 2);
        l_a = l_a * esa + suma;
        l_b = l_b * esb + sumb;

#pragma unroll
        for (int j = 0; j < 16; j++) {
            acc[j][0] *= esa; acc[j][1] *= esa;
            acc[j][2] *= esb; acc[j][3] *= esb;
        }

        // ---- PV: P (pre-packed fp16) @ V, 1 mma per n-tile ----
#pragma unroll
        for (int kc = 0; kc < 4; kc++) {
            uint32_t ph[4] = { Pa[2*kc], Pb[2*kc], Pa[2*kc+1], Pb[2*kc+1] };
#pragma unroll
            for (int j = 0; j < 16; j++) {
                int rv = (j * 8 + g) * FLDV + kc * 8 + tg;
                uint32_t bf[2] = { wV[rv], wV[rv + 4] };
                HMMA(acc[j], ph, bf);
            }
        }

        // ---- retire prefetch; make next buffer visible ----
        if (t < mt) {
            asm volatile("cp.async.wait_group 0;");
            __syncthreads();
        }
        buf ^= 1;
    }

    // ---- normalize + write fp16 (b,s,h,d) ----
    float inva = 1.0f / l_a, invb = 1.0f / l_b;
    int rowa = m0 + rowbase + g, rowb = rowa + 8;
#pragma unroll
    for (int j = 0; j < 16; j++) {
        int col = j * 8 + 2 * tg;
        uint32_t h0 = packh(acc[j][0] * inva, acc[j][1] * inva);
        uint32_t h1 = packh(acc[j][2] * invb, acc[j][3] * invb);
        size_t da = (((size_t)b * Sc + rowa) * Hc + h) * HDc + col;
        size_t db = (((size_t)b * Sc + rowb) * Hc + h) * HDc + col;
        *(uint32_t*)(att + da) = h0;
        *(uint32_t*)(att + db) = h1;
    }
}

// ---------------------------------------------------------------------------
// Launch
// ---------------------------------------------------------------------------
extern "C" void kernel_launch(void* const* d_in, const int* in_sizes, int n_in,
                              void* d_out, int out_size)
{
    const float* x    = (const float*)d_in[0];
    const float* fcos = (const float*)d_in[1];
    const float* fsin = (const float*)d_in[2];
    // d_in[3] = mask (causality handled analytically)
    const float* WAq  = (const float*)d_in[4];
    const float* WAk  = (const float*)d_in[5];
    const float* WAv  = (const float*)d_in[6];
    const float* WBq  = (const float*)d_in[7];
    const float* WBk  = (const float*)d_in[8];
    const float* WBv  = (const float*)d_in[9];
    const float* Wo   = (const float*)d_in[10];
    // d_in[11] = start_pos (0)
    float* out = (float*)d_out;

    __half *gx, *gWT, *gWoT, *gatt, *gq, *gk, *gv, *gvT;
    float *gproj;
    cudaGetSymbolAddress((void**)&gx,    g_x);
    cudaGetSymbolAddress((void**)&gWT,   g_WT);
    cudaGetSymbolAddress((void**)&gWoT,  g_WoT);
    cudaGetSymbolAddress((void**)&gproj, g_proj);
    cudaGetSymbolAddress((void**)&gq,    g_q);
    cudaGetSymbolAddress((void**)&gk,    g_k);
    cudaGetSymbolAddress((void**)&gv,    g_v);
    cudaGetSymbolAddress((void**)&gvT,   g_vT);
    cudaGetSymbolAddress((void**)&gatt,  g_att);

    static int smem_set = 0;
    if (!smem_set) {
        cudaFuncSetAttribute(f16_gemm_kernel,
                             cudaFuncAttributeMaxDynamicSharedMemorySize,
                             GSMEM_BYTES);
        cudaFuncSetAttribute(flash_kernel,
                             cudaFuncAttributeMaxDynamicSharedMemorySize,
                             FSMEM_BYTES);
        smem_set = 1;
    }

    const int M = Bc * Sc;   // 4096
    dim3 tsb(32, 8);

    // 0) Convert x to fp16; transpose ALL weights in one launch
    {
        long long n4 = (long long)Bc * Sc * Dc / 4;
        cvt_kernel<<<(unsigned)((n4 + 255) / 256), 256>>>(x, gx, n4);
    }
    tsplit_all_kernel<<<dim3(136, 64), tsb>>>(WAq, WAk, WAv, WBq, WBk, WBv, Wo,
                                              gWT, gWoT);

    // 1) Fused projection GEMM (single-mma fp16)
    {
        dim3 g(NTOT / GBN, M / GBM);
        f16_gemm_kernel<<<g, 256, GSMEM_BYTES>>>(gx, gWT, gproj, M, NTOT, Dc, NTOT);
    }

    // 2) Fused RoPE + rank combine -> fp16 q, k, v
    {
        long long tot = (long long)Bc * Sc * Hc * (HDc / 2);
        combine_kernel<<<(unsigned)((tot + 255) / 256), 256>>>(gproj, fcos, fsin,
                                                               gq, gk, gv);
    }

    // 2b) V transpose -> (b,h,d,s)
    vtrans_kernel<<<dim3(Sc/32, HDc/32, Bc*Hc), tsb>>>(gv, gvT);

    // 3) Flash attention (single-mma fp16, double-buffered) -> att fp16
    {
        dim3 g(Sc / 64, Bc * Hc);
        flash_kernel<<<g, 128, FSMEM_BYTES>>>(gq, gk, gvT, gatt);
    }

    // 4) Output projection (single-mma fp16) -> d_out
    {
        dim3 g(Dc / GBN, M / GBM);
        f16_gemm_kernel<<<g, 256, GSMEM_BYTES>>>(gatt, gWoT, out, M, Dc, Dc, Dc);
    }
}

// round 16
// speedup vs baseline: 1.0692x; 1.0692x over previous
#include <cuda_runtime.h>
#include <cuda_bf16.h>
#include <cuda_fp16.h>
#include <cstdint>

// Problem constants
#define Bc  2
#define Sc  2048
#define Dc  2048
#define Hc  16
#define HDc 128
#define QRc 12
#define Rc  2

// Fused projection column offsets: [WAq | WAk | WAv | WBq | WBk | WBv]
#define NTOT 2304
#define OAq  0
#define OAk  192
#define OAv  224
#define OBq  256
#define OBk  1792
#define OBv  2048

// ---------------------------------------------------------------------------
// Device scratch (no cudaMalloc allowed).
// ---------------------------------------------------------------------------
__device__ __half g_x  [(size_t)Bc*Sc*Dc];
__device__ __half g_WT [(size_t)NTOT*Dc];
__device__ __half g_WoT[(size_t)Dc*Dc];
__device__ float g_proj[(size_t)Bc*Sc*NTOT];
__device__ __half g_q  [(size_t)Bc*Sc*Hc*HDc];
__device__ __half g_k  [(size_t)Bc*Sc*Hc*HDc];
__device__ __half g_v  [(size_t)Bc*Sc*Hc*HDc];
__device__ __half g_vT [(size_t)Bc*Hc*HDc*Sc];
__device__ __half g_att[(size_t)Bc*Sc*Hc*HDc];

// ---------------------------------------------------------------------------
// Helpers
// ---------------------------------------------------------------------------
__device__ __forceinline__ uint32_t s2u(const void* p) {
    return (uint32_t)__cvta_generic_to_shared(p);
}
__device__ __forceinline__ void cp16(uint32_t dst, const void* src) {
    asm volatile("cp.async.cg.shared.global [%0], [%1], 16;\n"
                 :: "r"(dst), "l"(src));
}
__device__ __forceinline__ uint32_t packh(float a, float b) {
    __half2 t = __floats2half2_rn(a, b);
    return *(uint32_t*)&t;
}
// Two fp16 exps in one MUFU op: d = 2^(f16x2 of (a,b))
__device__ __forceinline__ uint32_t ex2h2(float a, float b) {
    uint32_t arg, r;
    asm("cvt.rn.f16x2.f32 %0, %1, %2;" : "=r"(arg) : "f"(b), "f"(a));
    asm("ex2.approx.f16x2 %0, %1;" : "=r"(r) : "r"(arg));
    return r;
}

// fp16 mma
#define HMMA(d, a, b) asm volatile( \
    "mma.sync.aligned.m16n8k16.row.col.f32.f16.f16.f32 " \
    "{%0,%1,%2,%3}, {%4,%5,%6,%7}, {%8,%9}, {%0,%1,%2,%3};" \
    : "+f"((d)[0]), "+f"((d)[1]), "+f"((d)[2]), "+f"((d)[3]) \
    : "r"((a)[0]), "r"((a)[1]), "r"((a)[2]), "r"((a)[3]), \
      "r"((b)[0]), "r"((b)[1]))

// ---------------------------------------------------------------------------
// Elementwise convert: fp32 -> fp16. n4 = elements/4.
// ---------------------------------------------------------------------------
__global__ void cvt_kernel(const float* __restrict__ src,
                           __half* __restrict__ dst, long long n4)
{
    long long i = (long long)blockIdx.x * blockDim.x + threadIdx.x;
    if (i >= n4) return;
    float4 f = ((const float4*)src)[i];
    ((__half2*)dst)[2*i]   = __floats2half2_rn(f.x, f.y);
    ((__half2*)dst)[2*i+1] = __floats2half2_rn(f.z, f.w);
}

// ---------------------------------------------------------------------------
// Merged transpose of ALL weights to fp16 [N][K] rows in one launch.
// ---------------------------------------------------------------------------
__global__ void tsplit_all_kernel(const float* __restrict__ W0,
                                  const float* __restrict__ W1,
                                  const float* __restrict__ W2,
                                  const float* __restrict__ W3,
                                  const float* __restrict__ W4,
                                  const float* __restrict__ W5,
                                  const float* __restrict__ W6,
                                  __half* __restrict__ WT,
                                  __half* __restrict__ WoT)
{
    const int segStart[8] = {0, 192, 224, 256, 1792, 2048, 2304, 4352};
    const float* srcs[7]  = {W0, W1, W2, W3, W4, W5, W6};
    const int Ns[7]       = {192, 32, 32, 1536, 256, 256, 2048};

    int cg = blockIdx.x * 32;
    int seg = 0;
#pragma unroll
    for (int s = 0; s < 6; s++)
        if (cg >= segStart[s + 1]) seg = s + 1;

    const float* W = srcs[seg];
    int N  = Ns[seg];
    int n0 = cg - segStart[seg];
    int k0 = blockIdx.y * 32;

    __shared__ float tile[32][33];
    int tx = threadIdx.x, ty = threadIdx.y;
    for (int r = ty; r < 32; r += 8)
        tile[r][tx] = W[(size_t)(k0 + r) * N + n0 + tx];
    __syncthreads();

    if (seg < 6) {
        for (int r = ty; r < 32; r += 8)
            WT[(size_t)(cg + r) * Dc + k0 + tx] = __float2half_rn(tile[tx][r]);
    } else {
        for (int r = ty; r < 32; r += 8)
            WoT[(size_t)(n0 + r) * Dc + k0 + tx] = __float2half_rn(tile[tx][r]);
    }
}

// ---------------------------------------------------------------------------
// Single-mma fp16 tensor-core GEMM (validated round 12, unchanged).
// ---------------------------------------------------------------------------
#define GBM 128
#define GBN 128
#define GBK 32
#define LDW 20
#define TW  (128 * LDW)
#define GSMEM_BYTES (2 * 2 * TW * 4) // 40960

__global__ __launch_bounds__(256) void f16_gemm_kernel(
    const __half* __restrict__ Ah, const __half* __restrict__ Bh,
    float* __restrict__ C, int M, int N, int K, int ldc)
{
    extern __shared__ uint32_t gs[];

    int m0 = blockIdx.y * GBM;
    int n0 = blockIdx.x * GBN;
    int tid = threadIdx.x, warp = tid >> 5, lane = tid & 31;
    int wm = warp >> 2, wn = warp & 3;
    int g  = lane >> 2, tg = lane & 3;

    float acc[4][4][4];
#pragma unroll
    for (int i = 0; i < 4; i++)
#pragma unroll
        for (int j = 0; j < 4; j++)
#pragma unroll
            for (int c = 0; c < 4; c++) acc[i][j][c] = 0.f;

    auto stage = [&](int kt, int buf) {
        uint32_t* base = gs + buf * 2 * TW;
        const __half* srcs[2] = {Ah, Bh};
#pragma unroll
        for (int t = 0; t < 2; t++) {
            const __half* S = srcs[t];
            int r0 = (t < 1) ? m0 : n0;
            uint32_t* dst = base + t * TW;
#pragma unroll
            for (int l = 0; l < 2; l++) {
                int v = tid + l * 256;
                int row = v >> 2, cq = v & 3;
                cp16(s2u(dst + row * LDW + cq * 4),
                     S + (size_t)(r0 + row) * K + kt + cq * 8);
            }
        }
    };

    stage(0, 0);
    asm volatile("cp.async.commit_group;");

    int buf = 0;
    for (int kt = 0; kt < K; kt += GBK, buf ^= 1) {
        if (kt + GBK < K) {
            stage(kt + GBK, buf ^ 1);
            asm volatile("cp.async.commit_group;");
            asm volatile("cp.async.wait_group 1;");
        } else {
            asm volatile("cp.async.wait_group 0;");
        }
        __syncthreads();

        const uint32_t* cA = gs + buf * 2 * TW;
        const uint32_t* cB = cA + TW;

#pragma unroll
        for (int ks = 0; ks < 2; ks++) {
            int kw = ks * 8;
            uint32_t ah[4][4], bh[4][2];
#pragma unroll
            for (int i = 0; i < 4; i++) {
                int b0 = (wm * 64 + i * 16 + g) * LDW + kw + tg;
                int b1 = b0 + 8 * LDW;
                ah[i][0] = cA[b0]; ah[i][1] = cA[b1];
                ah[i][2] = cA[b0 + 4]; ah[i][3] = cA[b1 + 4];
            }
#pragma unroll
            for (int j = 0; j < 4; j++) {
                int bb = (wn * 32 + j * 8 + g) * LDW + kw + tg;
                bh[j][0] = cB[bb]; bh[j][1] = cB[bb + 4];
            }
#pragma unroll
            for (int i = 0; i < 4; i++)
#pragma unroll
                for (int j = 0; j < 4; j++)
                    HMMA(acc[i][j], ah[i], bh[j]);
        }
        __syncthreads();
    }

#pragma unroll
    for (int i = 0; i < 4; i++) {
        int row = m0 + wm * 64 + i * 16 + g;
#pragma unroll
        for (int j = 0; j < 4; j++) {
            int col = n0 + wn * 32 + j * 8 + 2 * tg;
            *(float2*)(C + (size_t)row * ldc + col) =
                make_float2(acc[i][j][0], acc[i][j][1]);
            *(float2*)(C + (size_t)(row + 8) * ldc + col) =
                make_float2(acc[i][j][2], acc[i][j][3]);
        }
    }
}

// ---------------------------------------------------------------------------
// Fused RoPE + rank combine, SMEM-CACHED: one block per (b,s) row.
// Stage the 2304-float proj row + cos/sin into smem once (coalesced), then
// serve all 1024 (h, d-pair) outputs from smem (redundant reads become
// broadcasts instead of L1 traffic).
// ---------------------------------------------------------------------------
__global__ __launch_bounds__(256) void combine_kernel(
    const float* __restrict__ proj,
    const float* __restrict__ fcos, const float* __restrict__ fsin,
    __half* __restrict__ q, __half* __restrict__ k, __half* __restrict__ v)
{
    __shared__ float srow[NTOT];
    __shared__ float sco[HDc / 2], ssn[HDc / 2];

    long long bs = blockIdx.x;
    long long s  = bs % Sc;
    int tid = threadIdx.x;
    const float* row = proj + bs * NTOT;

    for (int i = tid; i < NTOT; i += 256) srow[i] = row[i];
    if (tid < HDc / 2) {
        sco[tid] = fcos[s * (HDc / 2) + tid];
        ssn[tid] = fsin[s * (HDc / 2) + tid];
    }
    __syncthreads();

    const float qs = (1.0f / QRc) * 0.08838834764831845f;
#pragma unroll
    for (int j = 0; j < 4; j++) {
        int o = tid + j * 256;          // 0..1023 = (h, d-pair)
        int h = o >> 6;
        int i = o & 63;
        float co = sco[i], sn = ssn[i];
        int d0 = 2 * i;

        float q0 = 0.f, q1 = 0.f;
#pragma unroll
        for (int r = 0; r < QRc; r++) {
            float a  = srow[OAq + h * QRc + r];
            float b0 = srow[OBq + r * HDc + d0];
            float b1 = srow[OBq + r * HDc + d0 + 1];
            q0 += a * (b0 * co - b1 * sn);
            q1 += a * (b0 * sn + b1 * co);
        }
        size_t base = (bs * Hc + h) * (size_t)HDc + d0;
        *(__half2*)(q + base) = __floats2half2_rn(q0 * qs, q1 * qs);

        float k0 = 0.f, k1 = 0.f, v0 = 0.f, v1 = 0.f;
#pragma unroll
        for (int r = 0; r < Rc; r++) {
            float ak = srow[OAk + h * Rc + r];
            float b0 = srow[OBk + r * HDc + d0];
            float b1 = srow[OBk + r * HDc + d0 + 1];
            k0 += ak * (b0 * co - b1 * sn);
            k1 += ak * (b0 * sn + b1 * co);
            float av = srow[OAv + h * Rc + r];
            v0 += av * srow[OBv + r * HDc + d0];
            v1 += av * srow[OBv + r * HDc + d0 + 1];
        }
        *(__half2*)(k + base) = __floats2half2_rn(k0 * (1.0f / Rc), k1 * (1.0f / Rc));
        *(__half2*)(v + base) = __floats2half2_rn(v0 * (1.0f / Rc), v1 * (1.0f / Rc));
    }
}

// ---------------------------------------------------------------------------
// V transpose: (b,s,h,d) -> (b,h,d,s), fp16.
// ---------------------------------------------------------------------------
__global__ void vtrans_kernel(const __half* __restrict__ v,
                              __half* __restrict__ vT)
{
    __shared__ __half th[32][34];
    int s0 = blockIdx.x * 32, d0 = blockIdx.y * 32;
    int bh = blockIdx.z;
    int b = bh / Hc, h = bh % Hc;
    int tx = threadIdx.x, ty = threadIdx.y;
    for (int r = ty; r < 32; r += 8)
        th[r][tx] = v[(((size_t)b * Sc + s0 + r) * Hc + h) * HDc + d0 + tx];
    __syncthreads();
    for (int r = ty; r < 32; r += 8)
        vT[((size_t)bh * HDc + d0 + r) * Sc + s0 + tx] = th[tx][r];
}

// ---------------------------------------------------------------------------
// Fused causal flash attention, single-mma fp16 (round-14 version verbatim —
// single-buffered; measured best at 596us. smem 53 KB).
// ---------------------------------------------------------------------------
#define FLDQ 68
#define FLDV 36
#define FQW  (64 * FLDQ)
#define FVW  (128 * FLDV)
#define FSMEM_BYTES ((2 * FQW + FVW) * 4)   // 53248

__global__ __launch_bounds__(128) void flash_kernel(
    const __half* __restrict__ q, const __half* __restrict__ kk_,
    const __half* __restrict__ vT, __half* __restrict__ att)
{
    extern __shared__ uint32_t fs[];
    uint32_t* wQ = fs;
    uint32_t* wK = wQ + FQW;
    uint32_t* wV = wK + FQW;

    int mt = gridDim.x - 1 - blockIdx.x;     // long blocks first
    int m0 = mt * 64;
    int bh = blockIdx.y;
    int b  = bh / Hc, h = bh % Hc;

    int tid  = threadIdx.x;
    int warp = tid >> 5, lane = tid & 31;
    int g = lane >> 2, tg = lane & 3;
    int rowbase = warp * 16;

    const float L2E = 1.4426950408889634f;

    // ---- stage Q (once), fully drained ----
#pragma unroll
    for (int l = 0; l < 8; l++) {
        int v = tid + l * 128;
        int row = v >> 4, cq = v & 15;
        size_t src = (((size_t)b * Sc + m0 + row) * Hc + h) * HDc + cq * 8;
        cp16(s2u(wQ + row * FLDQ + cq * 4), q + src);
    }
    asm volatile("cp.async.commit_group;");
    asm volatile("cp.async.wait_group 0;");
    __syncthreads();

    float acc[16][4];
#pragma unroll
    for (int j = 0; j < 16; j++)
#pragma unroll
        for (int c = 0; c < 4; c++) acc[j][c] = 0.f;
    float m_a = -1e30f, m_b = -1e30f, l_a = 0.f, l_b = 0.f;

    for (int t = 0; t <= mt; t++) {
        int n0 = t * 64;

        __syncthreads();
#pragma unroll
        for (int l = 0; l < 8; l++) {
            int v = tid + l * 128;
            int row = v >> 4, cq = v & 15;
            size_t src = (((size_t)b * Sc + n0 + row) * Hc + h) * HDc + cq * 8;
            cp16(s2u(wK + row * FLDQ + cq * 4), kk_ + src);
        }
#pragma unroll
        for (int l = 0; l < 8; l++) {
            int v = tid + l * 128;
            int row = v >> 3, cq = v & 7;
            size_t src = ((size_t)bh * HDc + row) * Sc + n0 + cq * 8;
            cp16(s2u(wV + row * FLDV + cq * 4), vT + src);
        }
        asm volatile("cp.async.commit_group;");
        asm volatile("cp.async.wait_group 0;");
        __syncthreads();

        // ---- S = Q K^T, 8 n-tiles of n8, 1 mma each ----
        float c[8][4];
#pragma unroll
        for (int n = 0; n < 8; n++)
#pragma unroll
            for (int i = 0; i < 4; i++) c[n][i] = 0.f;

#pragma unroll
        for (int kk = 0; kk < 8; kk++) {
            uint32_t ah[4];
            int ra = (rowbase + g) * FLDQ + kk * 8 + tg;
            int rb = (rowbase + g + 8) * FLDQ + kk * 8 + tg;
            ah[0] = wQ[ra]; ah[1] = wQ[rb]; ah[2] = wQ[ra + 4]; ah[3] = wQ[rb + 4];
#pragma unroll
            for (int n = 0; n < 8; n++) {
                int rk = (n * 8 + g) * FLDQ + kk * 8 + tg;
                uint32_t bf[2] = { wK[rk], wK[rk + 4] };
                HMMA(c[n], ah, bf);
            }
        }

        // ---- causal mask on the diagonal tile ----
        if (t == mt) {
            int ra = rowbase + g, rb = ra + 8;
#pragma unroll
            for (int n = 0; n < 8; n++) {
                int c0 = n * 8 + 2 * tg, c1 = c0 + 1;
                if (c0 > ra) c[n][0] = -1e30f;
                if (c1 > ra) c[n][1] = -1e30f;
                if (c0 > rb) c[n][2] = -1e30f;
                if (c1 > rb) c[n][3] = -1e30f;
            }
        }

        // ---- online softmax: max in fp32, exp via ex2.f16x2 ----
        float mxa = -1e30f, mxb = -1e30f;
#pragma unroll
        for (int n = 0; n < 8; n++) {
            mxa = fmaxf(mxa, fmaxf(c[n][0], c[n][1]));
            mxb = fmaxf(mxb, fmaxf(c[n][2], c[n][3]));
        }
        mxa = fmaxf(mxa, __shfl_xor_sync(0xFFFFFFFFu, mxa, 1));
        mxa = fmaxf(mxa, __shfl_xor_sync(0xFFFFFFFFu, mxa, 2));
        mxb = fmaxf(mxb, __shfl_xor_sync(0xFFFFFFFFu, mxb, 1));
        mxb = fmaxf(mxb, __shfl_xor_sync(0xFFFFFFFFu, mxb, 2));

        float mna = fmaxf(m_a, mxa), mnb = fmaxf(m_b, mxb);
        float esa = __expf(m_a - mna), esb = __expf(m_b - mnb);
        m_a = mna; m_b = mnb;

        float na = mna * L2E, nb = mnb * L2E;
        uint32_t Pa[8], Pb[8];
        __half2 sa = __floats2half2_rn(0.f, 0.f);
        __half2 sb = sa;
#pragma unroll
        for (int n = 0; n < 8; n++) {
            Pa[n] = ex2h2(fmaf(c[n][0], L2E, -na), fmaf(c[n][1], L2E, -na));
            Pb[n] = ex2h2(fmaf(c[n][2], L2E, -nb), fmaf(c[n][3], L2E, -nb));
            sa = __hadd2(sa, *(__half2*)&Pa[n]);
            sb = __hadd2(sb, *(__half2*)&Pb[n]);
        }
        float2 fa = __half22float2(sa);
        float2 fb = __half22float2(sb);
        float suma = fa.x + fa.y;
        float sumb = fb.x + fb.y;
        suma += __shfl_xor_sync(0xFFFFFFFFu, suma, 1);
        suma += __shfl_xor_sync(0xFFFFFFFFu, suma, 2);
        sumb += __shfl_xor_sync(0xFFFFFFFFu, sumb, 1);
        sumb += __shfl_xor_sync(0xFFFFFFFFu, sumb, 2);
        l_a = l_a * esa + suma;
        l_b = l_b * esb + sumb;

#pragma unroll
        for (int j = 0; j < 16; j++) {
            acc[j][0] *= esa; acc[j][1] *= esa;
            acc[j][2] *= esb; acc[j][3] *= esb;
        }

        // ---- PV: P (pre-packed fp16) @ V, 1 mma per n-tile ----
#pragma unroll
        for (int kc = 0; kc < 4; kc++) {
            uint32_t ph[4] = { Pa[2*kc], Pb[2*kc], Pa[2*kc+1], Pb[2*kc+1] };
#pragma unroll
            for (int j = 0; j < 16; j++) {
                int rv = (j * 8 + g) * FLDV + kc * 8 + tg;
                uint32_t bf[2] = { wV[rv], wV[rv + 4] };
                HMMA(acc[j], ph, bf);
            }
        }
    }

    // ---- normalize + write fp16 (b,s,h,d) ----
    float inva = 1.0f / l_a, invb = 1.0f / l_b;
    int rowa = m0 + rowbase + g, rowb = rowa + 8;
#pragma unroll
    for (int j = 0; j < 16; j++) {
        int col = j * 8 + 2 * tg;
        uint32_t h0 = packh(acc[j][0] * inva, acc[j][1] * inva);
        uint32_t h1 = packh(acc[j][2] * invb, acc[j][3] * invb);
        size_t da = (((size_t)b * Sc + rowa) * Hc + h) * HDc + col;
        size_t db = (((size_t)b * Sc + rowb) * Hc + h) * HDc + col;
        *(uint32_t*)(att + da) = h0;
        *(uint32_t*)(att + db) = h1;
    }
}

// ---------------------------------------------------------------------------
// Launch
// ---------------------------------------------------------------------------
extern "C" void kernel_launch(void* const* d_in, const int* in_sizes, int n_in,
                              void* d_out, int out_size)
{
    const float* x    = (const float*)d_in[0];
    const float* fcos = (const float*)d_in[1];
    const float* fsin = (const float*)d_in[2];
    // d_in[3] = mask (causality handled analytically)
    const float* WAq  = (const float*)d_in[4];
    const float* WAk  = (const float*)d_in[5];
    const float* WAv  = (const float*)d_in[6];
    const float* WBq  = (const float*)d_in[7];
    const float* WBk  = (const float*)d_in[8];
    const float* WBv  = (const float*)d_in[9];
    const float* Wo   = (const float*)d_in[10];
    // d_in[11] = start_pos (0)
    float* out = (float*)d_out;

    __half *gx, *gWT, *gWoT, *gatt, *gq, *gk, *gv, *gvT;
    float *gproj;
    cudaGetSymbolAddress((void**)&gx,    g_x);
    cudaGetSymbolAddress((void**)&gWT,   g_WT);
    cudaGetSymbolAddress((void**)&gWoT,  g_WoT);
    cudaGetSymbolAddress((void**)&gproj, g_proj);
    cudaGetSymbolAddress((void**)&gq,    g_q);
    cudaGetSymbolAddress((void**)&gk,    g_k);
    cudaGetSymbolAddress((void**)&gv,    g_v);
    cudaGetSymbolAddress((void**)&gvT,   g_vT);
    cudaGetSymbolAddress((void**)&gatt,  g_att);

    static int smem_set = 0;
    if (!smem_set) {
        cudaFuncSetAttribute(f16_gemm_kernel,
                             cudaFuncAttributeMaxDynamicSharedMemorySize,
                             GSMEM_BYTES);
        cudaFuncSetAttribute(flash_kernel,
                             cudaFuncAttributeMaxDynamicSharedMemorySize,
                             FSMEM_BYTES);
        smem_set = 1;
    }

    const int M = Bc * Sc;   // 4096
    dim3 tsb(32, 8);

    // 0) Convert x to fp16; transpose ALL weights in one launch
    {
        long long n4 = (long long)Bc * Sc * Dc / 4;
        cvt_kernel<<<(unsigned)((n4 + 255) / 256), 256>>>(x, gx, n4);
    }
    tsplit_all_kernel<<<dim3(136, 64), tsb>>>(WAq, WAk, WAv, WBq, WBk, WBv, Wo,
                                              gWT, gWoT);

    // 1) Fused projection GEMM (single-mma fp16)
    {
        dim3 g(NTOT / GBN, M / GBM);
        f16_gemm_kernel<<<g, 256, GSMEM_BYTES>>>(gx, gWT, gproj, M, NTOT, Dc, NTOT);
    }

    // 2) Fused RoPE + rank combine (smem-cached) -> fp16 q, k, v
    combine_kernel<<<Bc * Sc, 256>>>(gproj, fcos, fsin, gq, gk, gv);

    // 2b) V transpose -> (b,h,d,s)
    vtrans_kernel<<<dim3(Sc/32, HDc/32, Bc*Hc), tsb>>>(gv, gvT);

    // 3) Flash attention (single-mma fp16, single-buffered) -> att fp16
    {
        dim3 g(Sc / 64, Bc * Hc);
        flash_kernel<<<g, 128, FSMEM_BYTES>>>(gq, gk, gvT, gatt);
    }

    // 4) Output projection (single-mma fp16) -> d_out
    {
        dim3 g(Dc / GBN, M / GBM);
        f16_gemm_kernel<<<g, 256, GSMEM_BYTES>>>(gatt, gWoT, out, M, Dc, Dc, Dc);
    }
}